// round 1
// baseline (speedup 1.0000x reference)
#include <cuda_runtime.h>

// Problem constants (fixed by the module / dataset)
#define B_TOT 2048
#define H     51
#define R3    153          // 3*H gate rows
#define KP    52           // padded k stride (floats, float4-clean, pad = 0)
#define E     16           // batch elements per block
#define TPB   256          // threads: tx(16 elements) x ty(16 j-groups)
#define XCH   40           // x timesteps staged in smem per reload

struct Smem {
    float w1 [R3 * KP];    // w_hh1, rows padded to 52
    float wi2[R3 * KP];    // w_ih2
    float wh2[R3 * KP];    // w_hh2
    float wih1[156];       // w_ih1 (input dim 1 -> vector of 153)
    float brz1[104];       // b_ih1[j]+b_hh1[j] for r,z rows (layer 1)
    float bin1[52];        // b_ih1 n-rows
    float bhn1[52];        // b_hh1 n-rows
    float brz2[104];
    float bin2[52];
    float bhn2[52];
    float wlin[52];        // w_lin padded, pad = 0
    float h1[2][E][KP];    // ping-pong hidden states, pad stays 0
    float h2[2][E][KP];
    float xbuf[E][XCH];
    float outp[E];         // previous scalar output (phase-2 feedback)
    float blin;
};

__device__ __forceinline__ float sigmoid_(float v) {
    return __fdividef(1.0f, 1.0f + __expf(-v));
}
__device__ __forceinline__ float tanh_(float v) {
    return __fdividef(2.0f, 1.0f + __expf(-2.0f * v)) - 1.0f;
}

__global__ void __launch_bounds__(TPB, 1) gru_stack_kernel(
    const float* __restrict__ x,
    const float* __restrict__ w_ih1, const float* __restrict__ w_hh1,
    const float* __restrict__ b_ih1, const float* __restrict__ b_hh1,
    const float* __restrict__ w_ih2, const float* __restrict__ w_hh2,
    const float* __restrict__ b_ih2, const float* __restrict__ b_hh2,
    const float* __restrict__ w_lin, const float* __restrict__ b_lin,
    float* __restrict__ out, int T, int F)
{
    extern __shared__ float smem_f[];
    Smem* s = reinterpret_cast<Smem*>(smem_f);

    const int tid  = threadIdx.x;
    const int tx   = tid & 15;   // element within block
    const int ty   = tid >> 4;   // j group
    const int base = blockIdx.x * E;
    const int TF   = T + F;

    // ---- one-time init: weights -> smem (padded), combined biases, zero h ----
    for (int i = tid; i < R3 * KP; i += TPB) {
        int r = i / KP, k = i - r * KP;
        float a = 0.f, b = 0.f, c = 0.f;
        if (k < H) {
            a = w_hh1[r * H + k];
            b = w_ih2[r * H + k];
            c = w_hh2[r * H + k];
        }
        s->w1[i] = a; s->wi2[i] = b; s->wh2[i] = c;
    }
    for (int i = tid; i < R3; i += TPB) s->wih1[i] = w_ih1[i];
    for (int i = tid; i < 2 * H; i += TPB) {
        s->brz1[i] = b_ih1[i] + b_hh1[i];
        s->brz2[i] = b_ih2[i] + b_hh2[i];
    }
    for (int i = tid; i < H; i += TPB) {
        s->bin1[i] = b_ih1[2 * H + i];
        s->bhn1[i] = b_hh1[2 * H + i];
        s->bin2[i] = b_ih2[2 * H + i];
        s->bhn2[i] = b_hh2[2 * H + i];
    }
    for (int i = tid; i < KP; i += TPB) s->wlin[i] = (i < H) ? w_lin[i] : 0.f;
    if (tid == 0) s->blin = b_lin[0];
    {   // zero hidden buffers (incl. padding -> padding stays 0 forever)
        float* h1f = &s->h1[0][0][0];
        float* h2f = &s->h2[0][0][0];
        for (int i = tid; i < 2 * E * KP; i += TPB) { h1f[i] = 0.f; h2f[i] = 0.f; }
        for (int i = tid; i < E; i += TPB) s->outp[i] = 0.f;
    }
    __syncthreads();

    int cur = 0;
    for (int t = 0; t < TF; ++t) {
        // ---- stage a chunk of x into smem every XCH steps (phase 1 only) ----
        if (t < T && (t % XCH) == 0) {
            for (int i = tid; i < E * XCH; i += TPB) {
                int e = i / XCH, c = i - e * XCH;
                int tg = t + c;
                s->xbuf[e][c] = (tg < T) ? x[(size_t)(base + e) * T + tg] : 0.f;
            }
            __syncthreads();
        }

        const float xv = (t < T) ? s->xbuf[tx][t % XCH] : s->outp[tx];

        // ================= layer 1 (scalar input xv) =================
        {
            const float4* hv = reinterpret_cast<const float4*>(s->h1[cur][tx]);
            for (int j = ty; j < H; j += 16) {
                float ar  = fmaf(xv, s->wih1[j],         s->brz1[j]);
                float az  = fmaf(xv, s->wih1[H + j],     s->brz1[H + j]);
                float ain = fmaf(xv, s->wih1[2 * H + j], s->bin1[j]);
                float ahn = s->bhn1[j];
                const float4* wr = reinterpret_cast<const float4*>(&s->w1[j * KP]);
                const float4* wz = reinterpret_cast<const float4*>(&s->w1[(H + j) * KP]);
                const float4* wn = reinterpret_cast<const float4*>(&s->w1[(2 * H + j) * KP]);
                #pragma unroll
                for (int k4 = 0; k4 < KP / 4; ++k4) {
                    float4 h = hv[k4];
                    float4 a = wr[k4], b = wz[k4], c = wn[k4];
                    ar  = fmaf(h.x, a.x, ar);  ar  = fmaf(h.y, a.y, ar);
                    ar  = fmaf(h.z, a.z, ar);  ar  = fmaf(h.w, a.w, ar);
                    az  = fmaf(h.x, b.x, az);  az  = fmaf(h.y, b.y, az);
                    az  = fmaf(h.z, b.z, az);  az  = fmaf(h.w, b.w, az);
                    ahn = fmaf(h.x, c.x, ahn); ahn = fmaf(h.y, c.y, ahn);
                    ahn = fmaf(h.z, c.z, ahn); ahn = fmaf(h.w, c.w, ahn);
                }
                float r = sigmoid_(ar);
                float z = sigmoid_(az);
                float n = tanh_(fmaf(r, ahn, ain));
                float ho = s->h1[cur][tx][j];
                s->h1[cur ^ 1][tx][j] = fmaf(z, ho - n, n);  // (1-z)*n + z*h
            }
        }
        __syncthreads();

        // ================= layer 2 (vector input = new h1) =================
        {
            const float4* uv = reinterpret_cast<const float4*>(s->h1[cur ^ 1][tx]);
            const float4* vv = reinterpret_cast<const float4*>(s->h2[cur][tx]);
            for (int j = ty; j < H; j += 16) {
                float ar  = s->brz2[j];
                float az  = s->brz2[H + j];
                float ain = s->bin2[j];
                float ahn = s->bhn2[j];
                const float4* ir = reinterpret_cast<const float4*>(&s->wi2[j * KP]);
                const float4* iz = reinterpret_cast<const float4*>(&s->wi2[(H + j) * KP]);
                const float4* in = reinterpret_cast<const float4*>(&s->wi2[(2 * H + j) * KP]);
                const float4* hr = reinterpret_cast<const float4*>(&s->wh2[j * KP]);
                const float4* hz = reinterpret_cast<const float4*>(&s->wh2[(H + j) * KP]);
                const float4* hn = reinterpret_cast<const float4*>(&s->wh2[(2 * H + j) * KP]);
                #pragma unroll
                for (int k4 = 0; k4 < KP / 4; ++k4) {
                    float4 u = uv[k4], v = vv[k4];
                    float4 a = ir[k4], b = iz[k4], c = in[k4];
                    float4 d = hr[k4], e = hz[k4], f = hn[k4];
                    ar  = fmaf(u.x, a.x, ar);  ar  = fmaf(u.y, a.y, ar);
                    ar  = fmaf(u.z, a.z, ar);  ar  = fmaf(u.w, a.w, ar);
                    ar  = fmaf(v.x, d.x, ar);  ar  = fmaf(v.y, d.y, ar);
                    ar  = fmaf(v.z, d.z, ar);  ar  = fmaf(v.w, d.w, ar);
                    az  = fmaf(u.x, b.x, az);  az  = fmaf(u.y, b.y, az);
                    az  = fmaf(u.z, b.z, az);  az  = fmaf(u.w, b.w, az);
                    az  = fmaf(v.x, e.x, az);  az  = fmaf(v.y, e.y, az);
                    az  = fmaf(v.z, e.z, az);  az  = fmaf(v.w, e.w, az);
                    ain = fmaf(u.x, c.x, ain); ain = fmaf(u.y, c.y, ain);
                    ain = fmaf(u.z, c.z, ain); ain = fmaf(u.w, c.w, ain);
                    ahn = fmaf(v.x, f.x, ahn); ahn = fmaf(v.y, f.y, ahn);
                    ahn = fmaf(v.z, f.z, ahn); ahn = fmaf(v.w, f.w, ahn);
                }
                float r = sigmoid_(ar);
                float z = sigmoid_(az);
                float n = tanh_(fmaf(r, ahn, ain));
                float ho = s->h2[cur][tx][j];
                s->h2[cur ^ 1][tx][j] = fmaf(z, ho - n, n);
            }
        }
        __syncthreads();

        // ================= output linear (one thread per element) =================
        if (ty == 0) {
            const float4* hv = reinterpret_cast<const float4*>(s->h2[cur ^ 1][tx]);
            const float4* wl = reinterpret_cast<const float4*>(s->wlin);
            float acc = s->blin;
            #pragma unroll
            for (int k4 = 0; k4 < KP / 4; ++k4) {
                float4 h = hv[k4], w = wl[k4];
                acc = fmaf(h.x, w.x, acc); acc = fmaf(h.y, w.y, acc);
                acc = fmaf(h.z, w.z, acc); acc = fmaf(h.w, w.w, acc);
            }
            out[(size_t)(base + tx) * TF + t] = acc;
            s->outp[tx] = acc;
        }
        cur ^= 1;
        __syncthreads();
    }
}

extern "C" void kernel_launch(void* const* d_in, const int* in_sizes, int n_in,
                              void* d_out, int out_size)
{
    const float* x     = (const float*)d_in[0];
    const float* w_ih1 = (const float*)d_in[1];
    const float* w_hh1 = (const float*)d_in[2];
    const float* b_ih1 = (const float*)d_in[3];
    const float* b_hh1 = (const float*)d_in[4];
    const float* w_ih2 = (const float*)d_in[5];
    const float* w_hh2 = (const float*)d_in[6];
    const float* b_ih2 = (const float*)d_in[7];
    const float* b_hh2 = (const float*)d_in[8];
    const float* w_lin = (const float*)d_in[9];
    const float* b_lin = (const float*)d_in[10];

    const int B  = B_TOT;
    const int T  = in_sizes[0] / B;       // 1000
    const int TF = out_size / B;          // 2000
    const int F  = TF - T;                // 1000

    size_t shmem = sizeof(Smem);
    cudaFuncSetAttribute(gru_stack_kernel,
                         cudaFuncAttributeMaxDynamicSharedMemorySize, (int)shmem);

    gru_stack_kernel<<<B / E, TPB, shmem>>>(
        x, w_ih1, w_hh1, b_ih1, b_hh1,
        w_ih2, w_hh2, b_ih2, b_hh2,
        w_lin, b_lin, (float*)d_out, T, F);
}

// round 2
// speedup vs baseline: 1.3224x; 1.3224x over previous
#include <cuda_runtime.h>

#define B_TOT 2048
#define H     51
#define R3    153
#define KP    52           // padded row stride (floats), 13 float4 / ulonglong2
#define NK4   13           // KP/4
#define E     16           // elements per block
#define TPB   256
#define XCH   40

typedef unsigned long long ull;

struct Smem {
    float w1 [R3 * KP];    // w_hh1
    float wi2[R3 * KP];    // w_ih2
    float wh2[R3 * KP];    // w_hh2
    float wih1[160];       // w_ih1 (153 used)
    float brz1[104], bin1[52], bhn1[52];
    float brz2[104], bin2[52], bhn2[52];
    float wlin[52];
    float h1[2][E][KP];    // ping-pong, pad stays 0
    float h2[2][E][KP];
    float xbuf[E][XCH];
    float outp[E];
    float blin;
};

__device__ __forceinline__ void fma2(ull& d, ull a, ull b) {
    asm("fma.rn.f32x2 %0, %1, %2, %0;" : "+l"(d) : "l"(a), "l"(b));
}
__device__ __forceinline__ ull pack2(float a, float b) {
    ull r; asm("mov.b64 %0, {%1,%2};" : "=l"(r) : "f"(a), "f"(b)); return r;
}
__device__ __forceinline__ float sum2(ull v) {
    float a, b; asm("mov.b64 {%0,%1}, %2;" : "=f"(a), "=f"(b) : "l"(v));
    return a + b;
}
__device__ __forceinline__ float sigmoid_(float v) {
    return __fdividef(1.0f, 1.0f + __expf(-v));
}
__device__ __forceinline__ float tanh_(float v) {
    return __fdividef(2.0f, 1.0f + __expf(-2.0f * v)) - 1.0f;
}

__global__ void __launch_bounds__(TPB, 1) gru_stack_kernel(
    const float* __restrict__ x,
    const float* __restrict__ w_ih1, const float* __restrict__ w_hh1,
    const float* __restrict__ b_ih1, const float* __restrict__ b_hh1,
    const float* __restrict__ w_ih2, const float* __restrict__ w_hh2,
    const float* __restrict__ b_ih2, const float* __restrict__ b_hh2,
    const float* __restrict__ w_lin, const float* __restrict__ b_lin,
    float* __restrict__ out, int T, int F)
{
    extern __shared__ float smem_f[];
    Smem* s = reinterpret_cast<Smem*>(smem_f);

    const int tid  = threadIdx.x;
    const int tx   = tid & 3;          // element group: e = tx + 4i
    const int slot = tid >> 2;         // 0..63, 51 active j-slots
    const bool active = (slot % 5 != 4) && (slot != 63);
    const int j    = slot - slot / 5;  // bijection active-slot -> 0..50
    const int base = blockIdx.x * E;
    const int TF   = T + F;

    // ---- one-time init ----
    for (int i = tid; i < R3 * KP; i += TPB) {
        int r = i / KP, k = i - r * KP;
        float a = 0.f, b = 0.f, c = 0.f;
        if (k < H) {
            a = w_hh1[r * H + k];
            b = w_ih2[r * H + k];
            c = w_hh2[r * H + k];
        }
        s->w1[i] = a; s->wi2[i] = b; s->wh2[i] = c;
    }
    for (int i = tid; i < R3; i += TPB) s->wih1[i] = w_ih1[i];
    for (int i = tid; i < 2 * H; i += TPB) {
        s->brz1[i] = b_ih1[i] + b_hh1[i];
        s->brz2[i] = b_ih2[i] + b_hh2[i];
    }
    for (int i = tid; i < H; i += TPB) {
        s->bin1[i] = b_ih1[2 * H + i];
        s->bhn1[i] = b_hh1[2 * H + i];
        s->bin2[i] = b_ih2[2 * H + i];
        s->bhn2[i] = b_hh2[2 * H + i];
    }
    for (int i = tid; i < KP; i += TPB) s->wlin[i] = (i < H) ? w_lin[i] : 0.f;
    if (tid == 0) s->blin = b_lin[0];
    {
        float* h1f = &s->h1[0][0][0];
        float* h2f = &s->h2[0][0][0];
        for (int i = tid; i < 2 * E * KP; i += TPB) { h1f[i] = 0.f; h2f[i] = 0.f; }
        for (int i = tid; i < E; i += TPB) s->outp[i] = 0.f;
    }
    __syncthreads();

    int cur = 0;
    for (int t = 0; t < TF; ++t) {
        if (t < T && (t % XCH) == 0) {
            for (int i = tid; i < E * XCH; i += TPB) {
                int e = i / XCH, c = i - e * XCH;
                int tg = t + c;
                s->xbuf[e][c] = (tg < T) ? x[(size_t)(base + e) * T + tg] : 0.f;
            }
            __syncthreads();
        }
        const int xidx = t % XCH;

        // ================= layer 1 =================
        if (active) {
            ull ar[4], az[4], an[4];
            #pragma unroll
            for (int i = 0; i < 4; i++) {
                ar[i] = pack2(s->brz1[j], 0.f);
                az[i] = pack2(s->brz1[H + j], 0.f);
                an[i] = pack2(s->bhn1[j], 0.f);
            }
            const ulonglong2* wr = (const ulonglong2*)&s->w1[j * KP];
            const ulonglong2* wz = (const ulonglong2*)&s->w1[(H + j) * KP];
            const ulonglong2* wn = (const ulonglong2*)&s->w1[(2 * H + j) * KP];
            const ulonglong2* hp[4];
            #pragma unroll
            for (int i = 0; i < 4; i++)
                hp[i] = (const ulonglong2*)&s->h1[cur][tx + 4 * i][0];
            #pragma unroll
            for (int k = 0; k < NK4; k++) {
                ulonglong2 a = wr[k], b = wz[k], c = wn[k];
                #pragma unroll
                for (int i = 0; i < 4; i++) {
                    ulonglong2 h = hp[i][k];
                    fma2(ar[i], h.x, a.x); fma2(ar[i], h.y, a.y);
                    fma2(az[i], h.x, b.x); fma2(az[i], h.y, b.y);
                    fma2(an[i], h.x, c.x); fma2(an[i], h.y, c.y);
                }
            }
            const float wr1 = s->wih1[j], wz1 = s->wih1[H + j], wn1 = s->wih1[2 * H + j];
            const float bi = s->bin1[j];
            #pragma unroll
            for (int i = 0; i < 4; i++) {
                int e = tx + 4 * i;
                float xv = (t < T) ? s->xbuf[e][xidx] : s->outp[e];
                float gr  = fmaf(xv, wr1, sum2(ar[i]));
                float gz  = fmaf(xv, wz1, sum2(az[i]));
                float ghn = sum2(an[i]);
                float gin = fmaf(xv, wn1, bi);
                float r = sigmoid_(gr);
                float z = sigmoid_(gz);
                float n = tanh_(fmaf(r, ghn, gin));
                float ho = s->h1[cur][e][j];
                s->h1[cur ^ 1][e][j] = fmaf(z, ho - n, n);
            }
        }
        __syncthreads();

        // ================= layer 2 =================
        if (active) {
            ull ar[4], az[4], aI[4], aH[4];
            #pragma unroll
            for (int i = 0; i < 4; i++) {
                ar[i] = pack2(s->brz2[j], 0.f);
                az[i] = pack2(s->brz2[H + j], 0.f);
                aI[i] = pack2(s->bin2[j], 0.f);
                aH[i] = pack2(s->bhn2[j], 0.f);
            }
            const ulonglong2* ir  = (const ulonglong2*)&s->wi2[j * KP];
            const ulonglong2* iz  = (const ulonglong2*)&s->wi2[(H + j) * KP];
            const ulonglong2* in_ = (const ulonglong2*)&s->wi2[(2 * H + j) * KP];
            const ulonglong2* hr  = (const ulonglong2*)&s->wh2[j * KP];
            const ulonglong2* hz  = (const ulonglong2*)&s->wh2[(H + j) * KP];
            const ulonglong2* hn  = (const ulonglong2*)&s->wh2[(2 * H + j) * KP];
            const ulonglong2* up[4];
            const ulonglong2* vp[4];
            #pragma unroll
            for (int i = 0; i < 4; i++) {
                up[i] = (const ulonglong2*)&s->h1[cur ^ 1][tx + 4 * i][0];
                vp[i] = (const ulonglong2*)&s->h2[cur][tx + 4 * i][0];
            }
            #pragma unroll
            for (int k = 0; k < NK4; k++) {
                ulonglong2 a = ir[k], b = iz[k], c = in_[k];
                ulonglong2 d = hr[k], e2 = hz[k], f = hn[k];
                #pragma unroll
                for (int i = 0; i < 4; i++) {
                    ulonglong2 u = up[i][k];
                    ulonglong2 v = vp[i][k];
                    fma2(ar[i], u.x, a.x);  fma2(ar[i], u.y, a.y);
                    fma2(ar[i], v.x, d.x);  fma2(ar[i], v.y, d.y);
                    fma2(az[i], u.x, b.x);  fma2(az[i], u.y, b.y);
                    fma2(az[i], v.x, e2.x); fma2(az[i], v.y, e2.y);
                    fma2(aI[i], u.x, c.x);  fma2(aI[i], u.y, c.y);
                    fma2(aH[i], v.x, f.x);  fma2(aH[i], v.y, f.y);
                }
            }
            #pragma unroll
            for (int i = 0; i < 4; i++) {
                int e = tx + 4 * i;
                float r = sigmoid_(sum2(ar[i]));
                float z = sigmoid_(sum2(az[i]));
                float n = tanh_(fmaf(r, sum2(aH[i]), sum2(aI[i])));
                float ho = s->h2[cur][e][j];
                s->h2[cur ^ 1][e][j] = fmaf(z, ho - n, n);
            }
        }
        __syncthreads();

        // ================= output linear =================
        if (tid < E) {
            const ulonglong2* hv = (const ulonglong2*)&s->h2[cur ^ 1][tid][0];
            const ulonglong2* wl = (const ulonglong2*)&s->wlin[0];
            ull acc = pack2(s->blin, 0.f);
            #pragma unroll
            for (int k = 0; k < NK4; k++) {
                ulonglong2 h = hv[k], w = wl[k];
                fma2(acc, h.x, w.x); fma2(acc, h.y, w.y);
            }
            float o = sum2(acc);
            out[(size_t)(base + tid) * TF + t] = o;
            s->outp[tid] = o;
        }
        cur ^= 1;
        __syncthreads();
    }
}

extern "C" void kernel_launch(void* const* d_in, const int* in_sizes, int n_in,
                              void* d_out, int out_size)
{
    const float* x     = (const float*)d_in[0];
    const float* w_ih1 = (const float*)d_in[1];
    const float* w_hh1 = (const float*)d_in[2];
    const float* b_ih1 = (const float*)d_in[3];
    const float* b_hh1 = (const float*)d_in[4];
    const float* w_ih2 = (const float*)d_in[5];
    const float* w_hh2 = (const float*)d_in[6];
    const float* b_ih2 = (const float*)d_in[7];
    const float* b_hh2 = (const float*)d_in[8];
    const float* w_lin = (const float*)d_in[9];
    const float* b_lin = (const float*)d_in[10];

    const int B  = B_TOT;
    const int T  = in_sizes[0] / B;
    const int TF = out_size / B;
    const int F  = TF - T;

    size_t shmem = sizeof(Smem);
    cudaFuncSetAttribute(gru_stack_kernel,
                         cudaFuncAttributeMaxDynamicSharedMemorySize, (int)shmem);

    gru_stack_kernel<<<B / E, TPB, shmem>>>(
        x, w_ih1, w_hh1, b_ih1, b_hh1,
        w_ih2, w_hh2, b_ih2, b_hh2,
        w_lin, b_lin, (float*)d_out, T, F);
}

// round 3
// speedup vs baseline: 1.3776x; 1.0418x over previous
#include <cuda_runtime.h>

#define B_TOT 2048
#define H     51
#define HP    52           // padded gate rows (row 51 = zeros)
#define KP    56           // padded k stride per row (floats)
#define KU2   14           // KP in ulonglong2 units
#define PAIR  120          // floats per j-row-pair (2*56 + 8 pad)
#define NJG   26           // j-row-pair groups (covers 52 rows)
#define WSZ   (NJG*PAIR)   // floats per padded gate matrix = 3120
#define E     16           // elements per block
#define TPB   224          // 26 jg * 4 eg * 2 kh = 208 active (+16 clones)
#define XCH   40

typedef unsigned long long ull;

struct __align__(16) Smem {
    // padded gate matrices: row j at (j>>1)*PAIR + (j&1)*KP
    float l1r[WSZ], l1z[WSZ], l1n[WSZ];      // w_hh1
    float ir2[WSZ], iz2[WSZ], in2[WSZ];      // w_ih2
    float hr2[WSZ], hz2[WSZ], hn2[WSZ];      // w_hh2
    float wih1r[HP], wih1z[HP], wih1n[HP];   // w_ih1 columns (input dim 1)
    float bR1[HP], bZ1[HP], bIN1[HP], bHN1[HP];
    float bR2[HP], bZ2[HP], bIN2[HP], bHN2[HP];
    float wlin[KP];
    float h1[2][E][KP];                      // ping-pong, pads stay 0
    float h2[2][E][KP];
    float xbuf[E][XCH];
    float outp[E];
    float blin;
};

__device__ __forceinline__ void fma2(ull& d, ull a, ull b) {
    asm("fma.rn.f32x2 %0, %1, %2, %0;" : "+l"(d) : "l"(a), "l"(b));
}
__device__ __forceinline__ ull pack2(float a, float b) {
    ull r; asm("mov.b64 %0, {%1,%2};" : "=l"(r) : "f"(a), "f"(b)); return r;
}
__device__ __forceinline__ float sum2(ull v) {
    float a, b; asm("mov.b64 {%0,%1}, %2;" : "=f"(a), "=f"(b) : "l"(v));
    return a + b;
}
// combine k-halves across lane-bit0 partner, then horizontal sum
__device__ __forceinline__ float redsum(ull a) {
    ull o = __shfl_xor_sync(0xFFFFFFFFu, a, 1);
    ull r; asm("add.rn.f32x2 %0, %1, %2;" : "=l"(r) : "l"(a), "l"(o));
    return sum2(r);
}
__device__ __forceinline__ float sigmoid_(float v) {
    return __fdividef(1.0f, 1.0f + __expf(-v));
}
__device__ __forceinline__ float tanh_(float v) {
    return __fdividef(2.0f, 1.0f + __expf(-2.0f * v)) - 1.0f;
}

// fill one padded gate matrix (gate g of a [153][51] row-major source)
__device__ __forceinline__ void fill_mat(float* dst, const float* src, int g, int tid) {
    for (int idx = tid; idx < WSZ; idx += TPB) {
        int jg = idx / PAIR, rem = idx - jg * PAIR;
        int jj = rem / KP;                  // 0,1, or 2 => inter-pair pad
        int k  = rem - jj * KP;
        float v = 0.f;
        if (jj < 2) {
            int j = jg * 2 + jj;
            if (j < H && k < H) v = src[(g * H + j) * H + k];
        }
        dst[idx] = v;
    }
}

__global__ void __launch_bounds__(TPB, 1) gru_stack_kernel(
    const float* __restrict__ x,
    const float* __restrict__ w_ih1, const float* __restrict__ w_hh1,
    const float* __restrict__ b_ih1, const float* __restrict__ b_hh1,
    const float* __restrict__ w_ih2, const float* __restrict__ w_hh2,
    const float* __restrict__ b_ih2, const float* __restrict__ b_hh2,
    const float* __restrict__ w_lin, const float* __restrict__ b_lin,
    float* __restrict__ out, int T, int F)
{
    extern __shared__ float smem_f[];
    Smem* s = reinterpret_cast<Smem*>(smem_f);

    const int tid = threadIdx.x;
    const int kh  = tid & 1;                 // k-half
    const int eg  = (tid >> 1) & 3;          // element group: el = eg + 4*ei
    int jgt = tid >> 3; if (jgt > NJG - 1) jgt = NJG - 1;   // clone tail threads
    const int jg  = jgt;
    const int j0  = 2 * jg;                  // this thread's two gate rows: j0, j0+1
    const bool storer = (kh == 0) && (tid < 208);
    const int kb  = kh * (KU2 / 2);          // k-half offset in u2 units (7)
    const int base = blockIdx.x * E;
    const int TF   = T + F;

    // ---------------- one-time init ----------------
    fill_mat(s->l1r, w_hh1, 0, tid); fill_mat(s->l1z, w_hh1, 1, tid); fill_mat(s->l1n, w_hh1, 2, tid);
    fill_mat(s->ir2, w_ih2, 0, tid); fill_mat(s->iz2, w_ih2, 1, tid); fill_mat(s->in2, w_ih2, 2, tid);
    fill_mat(s->hr2, w_hh2, 0, tid); fill_mat(s->hz2, w_hh2, 1, tid); fill_mat(s->hn2, w_hh2, 2, tid);
    for (int i = tid; i < HP; i += TPB) {
        bool v = (i < H);
        s->wih1r[i] = v ? w_ih1[i] : 0.f;
        s->wih1z[i] = v ? w_ih1[H + i] : 0.f;
        s->wih1n[i] = v ? w_ih1[2 * H + i] : 0.f;
        s->bR1[i]  = v ? (b_ih1[i] + b_hh1[i]) : 0.f;
        s->bZ1[i]  = v ? (b_ih1[H + i] + b_hh1[H + i]) : 0.f;
        s->bIN1[i] = v ? b_ih1[2 * H + i] : 0.f;
        s->bHN1[i] = v ? b_hh1[2 * H + i] : 0.f;
        s->bR2[i]  = v ? (b_ih2[i] + b_hh2[i]) : 0.f;
        s->bZ2[i]  = v ? (b_ih2[H + i] + b_hh2[H + i]) : 0.f;
        s->bIN2[i] = v ? b_ih2[2 * H + i] : 0.f;
        s->bHN2[i] = v ? b_hh2[2 * H + i] : 0.f;
    }
    for (int i = tid; i < KP; i += TPB) s->wlin[i] = (i < H) ? w_lin[i] : 0.f;
    if (tid == 0) s->blin = b_lin[0];
    {
        float* h1f = &s->h1[0][0][0];
        float* h2f = &s->h2[0][0][0];
        for (int i = tid; i < 2 * E * KP; i += TPB) { h1f[i] = 0.f; h2f[i] = 0.f; }
        for (int i = tid; i < E; i += TPB) s->outp[i] = 0.f;
    }
    __syncthreads();

    int cur = 0;
    for (int t = 0; t < TF; ++t) {
        if (t < T && (t % XCH) == 0) {
            for (int i = tid; i < E * XCH; i += TPB) {
                int e = i / XCH, c = i - e * XCH;
                int tg = t + c;
                s->xbuf[e][c] = (tg < T) ? x[(size_t)(base + e) * T + tg] : 0.f;
            }
            __syncthreads();
        }
        const int xidx = t % XCH;
        const int nxt = cur ^ 1;

        // ================= layer 1: tile 2j x 4e, k-half =================
        {
            ull aR[2][4], aZ[2][4], aN[2][4];
            #pragma unroll
            for (int jj = 0; jj < 2; jj++)
                #pragma unroll
                for (int ei = 0; ei < 4; ei++) {
                    aR[jj][ei] = (kh == 0) ? pack2(s->bR1[j0 + jj], 0.f) : 0ull;
                    aZ[jj][ei] = (kh == 0) ? pack2(s->bZ1[j0 + jj], 0.f) : 0ull;
                    aN[jj][ei] = (kh == 0) ? pack2(s->bHN1[j0 + jj], 0.f) : 0ull;
                }
            const ulonglong2* pr = (const ulonglong2*)&s->l1r[jg * PAIR] + kb;
            const ulonglong2* pz = (const ulonglong2*)&s->l1z[jg * PAIR] + kb;
            const ulonglong2* pn = (const ulonglong2*)&s->l1n[jg * PAIR] + kb;
            const ulonglong2* ph = (const ulonglong2*)&s->h1[cur][0][0] + eg * KU2 + kb;
            #pragma unroll
            for (int ki = 0; ki < 7; ki++) {
                ulonglong2 w[6];
                w[0] = pr[ki]; w[1] = pr[ki + KU2];
                w[2] = pz[ki]; w[3] = pz[ki + KU2];
                w[4] = pn[ki]; w[5] = pn[ki + KU2];
                ulonglong2 hv[4];
                #pragma unroll
                for (int ei = 0; ei < 4; ei++) hv[ei] = ph[ki + ei * 4 * KU2];
                #pragma unroll
                for (int jj = 0; jj < 2; jj++)
                    #pragma unroll
                    for (int ei = 0; ei < 4; ei++) {
                        fma2(aR[jj][ei], hv[ei].x, w[0 + jj].x); fma2(aR[jj][ei], hv[ei].y, w[0 + jj].y);
                        fma2(aZ[jj][ei], hv[ei].x, w[2 + jj].x); fma2(aZ[jj][ei], hv[ei].y, w[2 + jj].y);
                        fma2(aN[jj][ei], hv[ei].x, w[4 + jj].x); fma2(aN[jj][ei], hv[ei].y, w[4 + jj].y);
                    }
            }
            float nh[2][4];
            #pragma unroll
            for (int jj = 0; jj < 2; jj++) {
                const float wr1 = s->wih1r[j0 + jj];
                const float wz1 = s->wih1z[j0 + jj];
                const float wn1 = s->wih1n[j0 + jj];
                const float bi  = s->bIN1[j0 + jj];
                #pragma unroll
                for (int ei = 0; ei < 4; ei++) {
                    int el = eg + 4 * ei;
                    float xv = (t < T) ? s->xbuf[el][xidx] : s->outp[el];
                    float gr  = fmaf(xv, wr1, redsum(aR[jj][ei]));
                    float gz  = fmaf(xv, wz1, redsum(aZ[jj][ei]));
                    float ghn = redsum(aN[jj][ei]);
                    float gin = fmaf(xv, wn1, bi);
                    float r = sigmoid_(gr);
                    float z = sigmoid_(gz);
                    float n = tanh_(fmaf(r, ghn, gin));
                    float ho = s->h1[cur][el][j0 + jj];
                    nh[jj][ei] = fmaf(z, ho - n, n);
                }
            }
            if (storer) {
                #pragma unroll
                for (int ei = 0; ei < 4; ei++) {
                    int el = eg + 4 * ei;
                    *(float2*)&s->h1[nxt][el][j0] = make_float2(nh[0][ei], nh[1][ei]);
                }
            }
        }
        __syncthreads();

        // ================= layer 2: tile 2j x 4e, k-half =================
        {
            ull aR[2][4], aZ[2][4], aI[2][4], aH[2][4];
            #pragma unroll
            for (int jj = 0; jj < 2; jj++)
                #pragma unroll
                for (int ei = 0; ei < 4; ei++) {
                    aR[jj][ei] = (kh == 0) ? pack2(s->bR2[j0 + jj], 0.f) : 0ull;
                    aZ[jj][ei] = (kh == 0) ? pack2(s->bZ2[j0 + jj], 0.f) : 0ull;
                    aI[jj][ei] = (kh == 0) ? pack2(s->bIN2[j0 + jj], 0.f) : 0ull;
                    aH[jj][ei] = (kh == 0) ? pack2(s->bHN2[j0 + jj], 0.f) : 0ull;
                }
            const ulonglong2* pir = (const ulonglong2*)&s->ir2[jg * PAIR] + kb;
            const ulonglong2* piz = (const ulonglong2*)&s->iz2[jg * PAIR] + kb;
            const ulonglong2* pin = (const ulonglong2*)&s->in2[jg * PAIR] + kb;
            const ulonglong2* phr = (const ulonglong2*)&s->hr2[jg * PAIR] + kb;
            const ulonglong2* phz = (const ulonglong2*)&s->hz2[jg * PAIR] + kb;
            const ulonglong2* phn = (const ulonglong2*)&s->hn2[jg * PAIR] + kb;
            const ulonglong2* pu  = (const ulonglong2*)&s->h1[nxt][0][0] + eg * KU2 + kb;
            const ulonglong2* pv  = (const ulonglong2*)&s->h2[cur][0][0] + eg * KU2 + kb;
            #pragma unroll
            for (int ki = 0; ki < 7; ki++) {
                ulonglong2 wi[6], wh[6];
                wi[0] = pir[ki]; wi[1] = pir[ki + KU2];
                wi[2] = piz[ki]; wi[3] = piz[ki + KU2];
                wi[4] = pin[ki]; wi[5] = pin[ki + KU2];
                wh[0] = phr[ki]; wh[1] = phr[ki + KU2];
                wh[2] = phz[ki]; wh[3] = phz[ki + KU2];
                wh[4] = phn[ki]; wh[5] = phn[ki + KU2];
                ulonglong2 uv[4], vv[4];
                #pragma unroll
                for (int ei = 0; ei < 4; ei++) {
                    uv[ei] = pu[ki + ei * 4 * KU2];
                    vv[ei] = pv[ki + ei * 4 * KU2];
                }
                #pragma unroll
                for (int jj = 0; jj < 2; jj++)
                    #pragma unroll
                    for (int ei = 0; ei < 4; ei++) {
                        fma2(aR[jj][ei], uv[ei].x, wi[0 + jj].x); fma2(aR[jj][ei], uv[ei].y, wi[0 + jj].y);
                        fma2(aR[jj][ei], vv[ei].x, wh[0 + jj].x); fma2(aR[jj][ei], vv[ei].y, wh[0 + jj].y);
                        fma2(aZ[jj][ei], uv[ei].x, wi[2 + jj].x); fma2(aZ[jj][ei], uv[ei].y, wi[2 + jj].y);
                        fma2(aZ[jj][ei], vv[ei].x, wh[2 + jj].x); fma2(aZ[jj][ei], vv[ei].y, wh[2 + jj].y);
                        fma2(aI[jj][ei], uv[ei].x, wi[4 + jj].x); fma2(aI[jj][ei], uv[ei].y, wi[4 + jj].y);
                        fma2(aH[jj][ei], vv[ei].x, wh[4 + jj].x); fma2(aH[jj][ei], vv[ei].y, wh[4 + jj].y);
                    }
            }
            float nh[2][4];
            #pragma unroll
            for (int jj = 0; jj < 2; jj++)
                #pragma unroll
                for (int ei = 0; ei < 4; ei++) {
                    int el = eg + 4 * ei;
                    float r = sigmoid_(redsum(aR[jj][ei]));
                    float z = sigmoid_(redsum(aZ[jj][ei]));
                    float n = tanh_(fmaf(r, redsum(aH[jj][ei]), redsum(aI[jj][ei])));
                    float ho = s->h2[cur][el][j0 + jj];
                    nh[jj][ei] = fmaf(z, ho - n, n);
                }
            if (storer) {
                #pragma unroll
                for (int ei = 0; ei < 4; ei++) {
                    int el = eg + 4 * ei;
                    *(float2*)&s->h2[nxt][el][j0] = make_float2(nh[0][ei], nh[1][ei]);
                }
            }
        }
        __syncthreads();

        // ================= output linear =================
        if (tid < E) {
            const ulonglong2* hv = (const ulonglong2*)&s->h2[nxt][tid][0];
            const ulonglong2* wl = (const ulonglong2*)&s->wlin[0];
            ull acc = pack2(s->blin, 0.f);
            #pragma unroll
            for (int k = 0; k < KU2; k++) {
                ulonglong2 h = hv[k], w = wl[k];
                fma2(acc, h.x, w.x); fma2(acc, h.y, w.y);
            }
            float o = sum2(acc);
            out[(size_t)(base + tid) * TF + t] = o;
            s->outp[tid] = o;
        }
        cur ^= 1;
        __syncthreads();
    }
}

extern "C" void kernel_launch(void* const* d_in, const int* in_sizes, int n_in,
                              void* d_out, int out_size)
{
    const float* x     = (const float*)d_in[0];
    const float* w_ih1 = (const float*)d_in[1];
    const float* w_hh1 = (const float*)d_in[2];
    const float* b_ih1 = (const float*)d_in[3];
    const float* b_hh1 = (const float*)d_in[4];
    const float* w_ih2 = (const float*)d_in[5];
    const float* w_hh2 = (const float*)d_in[6];
    const float* b_ih2 = (const float*)d_in[7];
    const float* b_hh2 = (const float*)d_in[8];
    const float* w_lin = (const float*)d_in[9];
    const float* b_lin = (const float*)d_in[10];

    const int B  = B_TOT;
    const int T  = in_sizes[0] / B;
    const int TF = out_size / B;
    const int F  = TF - T;

    size_t shmem = sizeof(Smem);
    cudaFuncSetAttribute(gru_stack_kernel,
                         cudaFuncAttributeMaxDynamicSharedMemorySize, (int)shmem);

    gru_stack_kernel<<<B / E, TPB, shmem>>>(
        x, w_ih1, w_hh1, b_ih1, b_hh1,
        w_ih2, w_hh2, b_ih2, b_hh2,
        w_lin, b_lin, (float*)d_out, T, F);
}